// round 12
// baseline (speedup 1.0000x reference)
#include <cuda_runtime.h>
#include <cuda_fp16.h>
#include <stdint.h>

#define RES    32
#define BATCH  2
#define LTOK   32768
#define CDIM   256
#define HEADS  8
#define HDV    32
#define SWIN   256
// scale * log2(e): exp(s) == 2^(s*log2e), folded into Q pre-scale
#define SCALEE 0.25505654201513125f

#define NT     128      // 4 fat warps x 64 query rows
#define HSTR_B 80       // fp16 tile row stride: 40 halves = 80B

// byte offsets in smem
#define QS_B   0        // Q fp16 [256][40]; O staging overlays QS+KS
#define KS_B   20480    // K fp16 [256][40]
#define VS_B   40960    // V fp16 [256][40]
#define W_B    61440    // conv w, 288 fp32
#define BI_B   62592    // conv b, 32 fp32
#define SMEM_BYTES 62720
// O staging: fp32 [256][36] overlaid on QS_B.. (spills into KS region ->
// __syncthreads() must separate main-loop K reads from staging writes)
#define OSTR   36

__device__ __forceinline__ uint32_t h2u(__half2 h) {
    return *reinterpret_cast<uint32_t*>(&h);
}
__device__ __forceinline__ uint32_t smem_u32(const void* p) {
    uint32_t a;
    asm("{ .reg .u64 t; cvta.to.shared.u64 t, %1; cvt.u32.u64 %0, t; }" : "=r"(a) : "l"(p));
    return a;
}
__device__ __forceinline__ uint32_t packh2(float hi, float lo) {
    uint32_t r;
    asm("cvt.rn.f16x2.f32 %0, %1, %2;" : "=r"(r) : "f"(hi), "f"(lo));
    return r;
}
__device__ __forceinline__ uint32_t ex2h2(uint32_t x) {
    uint32_t r;
    asm("ex2.approx.f16x2 %0, %1;" : "=r"(r) : "r"(x));
    return r;
}
__device__ __forceinline__ void ldsm4(uint32_t* r, uint32_t addr) {
    asm volatile("ldmatrix.sync.aligned.m8n8.x4.shared.b16 {%0,%1,%2,%3}, [%4];"
        : "=r"(r[0]), "=r"(r[1]), "=r"(r[2]), "=r"(r[3]) : "r"(addr));
}
__device__ __forceinline__ void ldsm4t(uint32_t* r, uint32_t addr) {
    asm volatile("ldmatrix.sync.aligned.m8n8.x4.trans.shared.b16 {%0,%1,%2,%3}, [%4];"
        : "=r"(r[0]), "=r"(r[1]), "=r"(r[2]), "=r"(r[3]) : "r"(addr));
}
__device__ __forceinline__ void sts64(uint32_t addr, uint32_t a, uint32_t b) {
    asm volatile("st.shared.v2.b32 [%0], {%1, %2};" :: "r"(addr), "r"(a), "r"(b) : "memory");
}
// D(f32) += A(f16) * B(f16),  m16n8k16
__device__ __forceinline__ void mma16(float* d, const uint32_t* a, const uint32_t* b) {
    asm("mma.sync.aligned.m16n8k16.row.col.f32.f16.f16.f32 "
        "{%0,%1,%2,%3}, {%4,%5,%6,%7}, {%8,%9}, {%0,%1,%2,%3};"
        : "+f"(d[0]), "+f"(d[1]), "+f"(d[2]), "+f"(d[3])
        : "r"(a[0]), "r"(a[1]), "r"(a[2]), "r"(a[3]), "r"(b[0]), "r"(b[1]));
}

__global__ void __launch_bounds__(NT, 2)
lepe_attn_h16(const float* __restrict__ qkv,
              const float* __restrict__ conv_w,
              const float* __restrict__ conv_b,
              float* __restrict__ out)
{
    extern __shared__ float smem[];
    char* smb = (char*)smem;
    float* Wsm = (float*)(smb + W_B);
    float* Bsm = (float*)(smb + BI_B);
    const uint32_t sb = smem_u32(smem);

    const int tid  = threadIdx.x;
    const int lane = tid & 31;
    const int warp = tid >> 5;       // 0..3
    const int g    = lane >> 2;
    const int tg   = lane & 3;
    const int m0   = warp * 64;      // 64 query rows per warp

    const int head = blockIdx.x & 7;
    const int wi   = blockIdx.x >> 3;
    const int b    = wi >> 7;
    const int dsl  = (wi >> 2) & 31;
    const int iw   = wi & 3;

    // ---- stage Q/K/V, coalesced: 8 lanes cooperate on one token row ----
    {
        const int piece = lane & 7;
        const int sub   = tid >> 3;           // 0..15
        const size_t qkv_k = (size_t)BATCH * LTOK * CDIM;
#pragma unroll
        for (int it = 0; it < 16; it++) {
            const int tok = it * 16 + sub;
            const int l = dsl * 1024 + (tok >> 3) * 32 + iw * 8 + (tok & 7);
            const size_t base = ((size_t)b * LTOK + l) * CDIM + head * HDV + piece * 4;
            const uint32_t sad = (uint32_t)(tok * HSTR_B + piece * 8);
            float4 qq = *(const float4*)(qkv + base);
            *(uint2*)(smb + QS_B + sad) = make_uint2(
                h2u(__floats2half2_rn(qq.x * SCALEE, qq.y * SCALEE)),
                h2u(__floats2half2_rn(qq.z * SCALEE, qq.w * SCALEE)));
            float4 kk = *(const float4*)(qkv + qkv_k + base);
            *(uint2*)(smb + KS_B + sad) = make_uint2(
                h2u(__floats2half2_rn(kk.x, kk.y)),
                h2u(__floats2half2_rn(kk.z, kk.w)));
            float4 vv = *(const float4*)(qkv + 2 * qkv_k + base);
            *(uint2*)(smb + VS_B + sad) = make_uint2(
                h2u(__floats2half2_rn(vv.x, vv.y)),
                h2u(__floats2half2_rn(vv.z, vv.w)));
        }
        for (int i = tid; i < 9 * HDV; i += NT) Wsm[i] = conv_w[head * HDV * 9 + i];
        if (tid < HDV) Bsm[tid] = conv_b[head * HDV + tid];
    }
    __syncthreads();

    const int lane7 = lane & 7;
    const int lb8   = (lane >> 3) & 1;
    const int lb16  = (lane >> 4) & 1;
    const uint32_t a_base = sb + QS_B + (uint32_t)(m0 + lane7 + lb8 * 8) * HSTR_B + lb16 * 16;
    const uint32_t k_base = sb + KS_B + (uint32_t)(lane7 + lb16 * 8) * HSTR_B + lb8 * 16;
    const uint32_t v_base = sb + VS_B + (uint32_t)(lane7 + lb8 * 8) * HSTR_B + lb16 * 16;
    const uint32_t o_st = sb + QS_B + ((uint32_t)(m0 + g) * OSTR + 2 * tg) * 4;

    // ---- Q fragments: 4 m-tiles x 2 k-steps ----
    uint32_t qf[4][2][4];
#pragma unroll
    for (int mt = 0; mt < 4; mt++)
#pragma unroll
        for (int ks = 0; ks < 2; ks++)
            ldsm4(qf[mt][ks], a_base + mt * (16 * HSTR_B) + ks * 32);

    float o[4][4][4];
    float rsacc[4][4];
    const uint32_t ones2[2] = {0x3C003C00u, 0x3C003C00u};
#pragma unroll
    for (int mt = 0; mt < 4; mt++) {
#pragma unroll
        for (int i = 0; i < 4; i++) rsacc[mt][i] = 0.f;
#pragma unroll
        for (int nt = 0; nt < 4; nt++)
#pragma unroll
            for (int i = 0; i < 4; i++) o[mt][nt][i] = 0.f;
    }

    // ---- main loop: 8 chunks of 32 keys; K/V frags shared across 4 m-tiles ----
    for (int c0 = 0; c0 < SWIN; c0 += 32) {
        uint32_t kf[2][2][4], vf[2][2][4];
#pragma unroll
        for (int ks = 0; ks < 2; ks++) {
            ldsm4(kf[ks][0], k_base + (uint32_t)(c0 * HSTR_B) + ks * 32);
            ldsm4(kf[ks][1], k_base + (uint32_t)((c0 + 16) * HSTR_B) + ks * 32);
        }
#pragma unroll
        for (int ks = 0; ks < 2; ks++) {
            ldsm4t(vf[ks][0], v_base + (uint32_t)((c0 + ks * 16) * HSTR_B));
            ldsm4t(vf[ks][1], v_base + (uint32_t)((c0 + ks * 16) * HSTR_B) + 32);
        }

#pragma unroll
        for (int mt = 0; mt < 4; mt++) {
            float p[4][4];
#pragma unroll
            for (int nt = 0; nt < 4; nt++)
#pragma unroll
                for (int i = 0; i < 4; i++) p[nt][i] = 0.f;

#pragma unroll
            for (int ks = 0; ks < 2; ks++) {
                mma16(p[0], qf[mt][ks], kf[ks][0]);
                mma16(p[1], qf[mt][ks], kf[ks][0] + 2);
                mma16(p[2], qf[mt][ks], kf[ks][1]);
                mma16(p[3], qf[mt][ks], kf[ks][1] + 2);
            }

            uint32_t af[2][4];
#pragma unroll
            for (int nt = 0; nt < 4; nt++) {
                af[nt >> 1][(nt & 1) * 2 + 0] = ex2h2(packh2(p[nt][1], p[nt][0]));
                af[nt >> 1][(nt & 1) * 2 + 1] = ex2h2(packh2(p[nt][3], p[nt][2]));
            }

            mma16(rsacc[mt], af[0], ones2);
            mma16(rsacc[mt], af[1], ones2);

#pragma unroll
            for (int ks = 0; ks < 2; ks++) {
                mma16(o[mt][0], af[ks], vf[ks][0]);
                mma16(o[mt][1], af[ks], vf[ks][0] + 2);
                mma16(o[mt][2], af[ks], vf[ks][1]);
                mma16(o[mt][3], af[ks], vf[ks][1] + 2);
            }
        }
    }

    // All warps must finish reading K/Q smem before O staging overwrites them.
    __syncthreads();

    // ---- normalize + staging (warp-local rows m0..m0+63) ----
#pragma unroll
    for (int mt = 0; mt < 4; mt++) {
        const float inv0 = 1.0f / rsacc[mt][0];   // rowsum(g)
        const float inv1 = 1.0f / rsacc[mt][2];   // rowsum(g+8)
#pragma unroll
        for (int nt = 0; nt < 4; nt++) {
            uint32_t ad = o_st + (mt * 16 * OSTR + nt * 8) * 4;
            sts64(ad, __float_as_uint(o[mt][nt][0] * inv0),
                      __float_as_uint(o[mt][nt][1] * inv0));
            sts64(ad + 8 * OSTR * 4, __float_as_uint(o[mt][nt][2] * inv1),
                                     __float_as_uint(o[mt][nt][3] * inv1));
        }
    }
    __syncwarp();

    // ---- epilogue: conv — warp = 2 tokens/iter over 64 tokens, lane = d2 pair ----
    {
        const int d2   = lane & 15;
        const int side = lane >> 4;
        float w0[9], w1[9];
#pragma unroll
        for (int t = 0; t < 9; t++) {
            w0[t] = Wsm[(2 * d2) * 9 + t];
            w1[t] = Wsm[(2 * d2 + 1) * 9 + t];
        }
        const float b0 = Bsm[2 * d2], b1 = Bsm[2 * d2 + 1];

#pragma unroll
        for (int it = 0; it < 32; it++) {
            const int tok = m0 + it * 2 + side;
            const int h = tok >> 3, w = tok & 7;
            float2 oo = *(const float2*)(smb + QS_B + (tok * OSTR + 2 * d2) * 4);
            float a0 = oo.x + b0;
            float a1 = oo.y + b1;
#pragma unroll
            for (int dh = -1; dh <= 1; dh++) {
                const int hh = h + dh;
                if (hh < 0 || hh >= RES) continue;
#pragma unroll
                for (int dw = -1; dw <= 1; dw++) {
                    const int ww = w + dw;
                    if (ww < 0 || ww >= 8) continue;
                    const int k = hh * 8 + ww;
                    const int t = (dh + 1) * 3 + (dw + 1);
                    float2 fv = __half22float2(
                        *(const __half2*)(smb + VS_B + k * HSTR_B + d2 * 4));
                    a0 += w0[t] * fv.x;
                    a1 += w1[t] * fv.y;
                }
            }
            const int l = dsl * 1024 + h * 32 + iw * 8 + w;
            float* op = out + ((size_t)b * LTOK + l) * CDIM + head * HDV + 2 * d2;
            *(float2*)op = make_float2(a0, a1);
        }
    }
}

extern "C" void kernel_launch(void* const* d_in, const int* in_sizes, int n_in,
                              void* d_out, int out_size)
{
    const float* qkv    = (const float*)d_in[0];
    const float* conv_w = (const float*)d_in[1];
    const float* conv_b = (const float*)d_in[2];
    float* out = (float*)d_out;

    cudaFuncSetAttribute(lepe_attn_h16,
                         cudaFuncAttributeMaxDynamicSharedMemorySize, SMEM_BYTES);
    lepe_attn_h16<<<2048, NT, SMEM_BYTES>>>(qkv, conv_w, conv_b, out);
}

// round 13
// speedup vs baseline: 1.1375x; 1.1375x over previous
#include <cuda_runtime.h>
#include <cuda_fp16.h>
#include <stdint.h>

#define RES    32
#define BATCH  2
#define LTOK   32768
#define CDIM   256
#define HEADS  8
#define HDV    32
#define SWIN   256
// scale * log2(e): exp(s) == 2^(s*log2e), folded into Q pre-scale
#define SCALEE 0.25505654201513125f

#define NT     256
#define HSTR_B 80      // fp16 tile row stride: 40 halves = 80B

// byte offsets in smem
#define QS_B   0        // Q fp16 [256][40]; later fp16 O staging (same footprint)
#define KS_B   20480    // K fp16 [256][40]
#define VS_B   40960    // V fp16 [256][40]
#define W_B    61440    // conv w, 288 fp32
#define BI_B   62592    // conv b, 32 fp32
#define SMEM_BYTES 62720

__device__ __forceinline__ uint32_t h2u(__half2 h) {
    return *reinterpret_cast<uint32_t*>(&h);
}
__device__ __forceinline__ uint32_t smem_u32(const void* p) {
    uint32_t a;
    asm("{ .reg .u64 t; cvta.to.shared.u64 t, %1; cvt.u32.u64 %0, t; }" : "=r"(a) : "l"(p));
    return a;
}
__device__ __forceinline__ uint32_t packh2(float hi, float lo) {
    uint32_t r;
    asm("cvt.rn.f16x2.f32 %0, %1, %2;" : "=r"(r) : "f"(hi), "f"(lo));
    return r;
}
__device__ __forceinline__ uint32_t ex2h2(uint32_t x) {
    uint32_t r;
    asm("ex2.approx.f16x2 %0, %1;" : "=r"(r) : "r"(x));
    return r;
}
__device__ __forceinline__ void ldsm4(uint32_t* r, uint32_t addr) {
    asm volatile("ldmatrix.sync.aligned.m8n8.x4.shared.b16 {%0,%1,%2,%3}, [%4];"
        : "=r"(r[0]), "=r"(r[1]), "=r"(r[2]), "=r"(r[3]) : "r"(addr));
}
__device__ __forceinline__ void ldsm4t(uint32_t* r, uint32_t addr) {
    asm volatile("ldmatrix.sync.aligned.m8n8.x4.trans.shared.b16 {%0,%1,%2,%3}, [%4];"
        : "=r"(r[0]), "=r"(r[1]), "=r"(r[2]), "=r"(r[3]) : "r"(addr));
}
__device__ __forceinline__ void sts32(uint32_t addr, uint32_t v) {
    asm volatile("st.shared.b32 [%0], %1;" :: "r"(addr), "r"(v) : "memory");
}
// D(f32) += A(f16) * B(f16),  m16n8k16
__device__ __forceinline__ void mma16(float* d, const uint32_t* a, const uint32_t* b) {
    asm("mma.sync.aligned.m16n8k16.row.col.f32.f16.f16.f32 "
        "{%0,%1,%2,%3}, {%4,%5,%6,%7}, {%8,%9}, {%0,%1,%2,%3};"
        : "+f"(d[0]), "+f"(d[1]), "+f"(d[2]), "+f"(d[3])
        : "r"(a[0]), "r"(a[1]), "r"(a[2]), "r"(a[3]), "r"(b[0]), "r"(b[1]));
}

__global__ void __launch_bounds__(NT, 2)
lepe_attn_h16(const float* __restrict__ qkv,
              const float* __restrict__ conv_w,
              const float* __restrict__ conv_b,
              float* __restrict__ out)
{
    extern __shared__ float smem[];
    char* smb = (char*)smem;
    float* Wsm = (float*)(smb + W_B);
    float* Bsm = (float*)(smb + BI_B);
    const uint32_t sb = smem_u32(smem);

    const int tid  = threadIdx.x;
    const int lane = tid & 31;
    const int warp = tid >> 5;
    const int g    = lane >> 2;
    const int tg   = lane & 3;
    const int m0   = warp * 32;

    const int head = blockIdx.x & 7;
    const int wi   = blockIdx.x >> 3;
    const int b    = wi >> 7;
    const int dsl  = (wi >> 2) & 31;
    const int iw   = wi & 3;

    // ---- stage Q/K/V, coalesced: 8 lanes cooperate on one token row ----
    {
        const int piece = lane & 7;
        const size_t qkv_k = (size_t)BATCH * LTOK * CDIM;
#pragma unroll
        for (int it = 0; it < 8; it++) {
            const int tok = m0 + it * 4 + (lane >> 3);
            const int l = dsl * 1024 + (tok >> 3) * 32 + iw * 8 + (tok & 7);
            const size_t base = ((size_t)b * LTOK + l) * CDIM + head * HDV + piece * 4;
            const uint32_t sad = (uint32_t)(tok * HSTR_B + piece * 8);
            float4 qq = *(const float4*)(qkv + base);
            *(uint2*)(smb + QS_B + sad) = make_uint2(
                h2u(__floats2half2_rn(qq.x * SCALEE, qq.y * SCALEE)),
                h2u(__floats2half2_rn(qq.z * SCALEE, qq.w * SCALEE)));
            float4 kk = *(const float4*)(qkv + qkv_k + base);
            *(uint2*)(smb + KS_B + sad) = make_uint2(
                h2u(__floats2half2_rn(kk.x, kk.y)),
                h2u(__floats2half2_rn(kk.z, kk.w)));
            float4 vv = *(const float4*)(qkv + 2 * qkv_k + base);
            *(uint2*)(smb + VS_B + sad) = make_uint2(
                h2u(__floats2half2_rn(vv.x, vv.y)),
                h2u(__floats2half2_rn(vv.z, vv.w)));
        }
        for (int i = tid; i < 9 * HDV; i += NT) Wsm[i] = conv_w[head * HDV * 9 + i];
        if (tid < HDV) Bsm[tid] = conv_b[head * HDV + tid];
    }
    __syncthreads();

    const int lane7 = lane & 7;
    const int lb8   = (lane >> 3) & 1;
    const int lb16  = (lane >> 4) & 1;
    const uint32_t a_base = sb + QS_B + (uint32_t)(m0 + lane7 + lb8 * 8) * HSTR_B + lb16 * 16;
    const uint32_t k_base = sb + KS_B + (uint32_t)(lane7 + lb16 * 8) * HSTR_B + lb8 * 16;
    const uint32_t v_base = sb + VS_B + (uint32_t)(lane7 + lb8 * 8) * HSTR_B + lb16 * 16;
    // fp16 O staging over Q region: row (m0+g) stride 80B, half2 at col 2tg
    const uint32_t o_st = sb + QS_B + (uint32_t)(m0 + g) * HSTR_B + tg * 4;

    // ---- Q fragments: 2 m-tiles x 2 k-steps ----
    uint32_t qf[2][2][4];
#pragma unroll
    for (int mt = 0; mt < 2; mt++)
#pragma unroll
        for (int ks = 0; ks < 2; ks++)
            ldsm4(qf[mt][ks], a_base + mt * (16 * HSTR_B) + ks * 32);

    float o[2][4][4];
    float rsacc[2][4];   // row sums via P x ones MMA: c0=rowsum(g), c2=rowsum(g+8)
    const uint32_t ones2[2] = {0x3C003C00u, 0x3C003C00u};
#pragma unroll
    for (int mt = 0; mt < 2; mt++) {
#pragma unroll
        for (int i = 0; i < 4; i++) rsacc[mt][i] = 0.f;
#pragma unroll
        for (int nt = 0; nt < 4; nt++)
#pragma unroll
            for (int i = 0; i < 4; i++) o[mt][nt][i] = 0.f;
    }

    // ---- main loop: 8 chunks of 32 keys ----
    for (int c0 = 0; c0 < SWIN; c0 += 32) {
        float p[2][4][4];
#pragma unroll
        for (int mt = 0; mt < 2; mt++)
#pragma unroll
            for (int nt = 0; nt < 4; nt++)
#pragma unroll
                for (int i = 0; i < 4; i++) p[mt][nt][i] = 0.f;

        // S = Q K^T
#pragma unroll
        for (int ks = 0; ks < 2; ks++) {
            uint32_t kf0[4], kf1[4];
            ldsm4(kf0, k_base + (uint32_t)(c0 * HSTR_B) + ks * 32);
            ldsm4(kf1, k_base + (uint32_t)((c0 + 16) * HSTR_B) + ks * 32);
#pragma unroll
            for (int mt = 0; mt < 2; mt++) {
                mma16(p[mt][0], qf[mt][ks], kf0);
                mma16(p[mt][1], qf[mt][ks], kf0 + 2);
                mma16(p[mt][2], qf[mt][ks], kf1);
                mma16(p[mt][3], qf[mt][ks], kf1 + 2);
            }
        }

        // V fragments hoisted: independent of exp chain, latency hides behind it
        uint32_t vf[2][2][4];
#pragma unroll
        for (int ks = 0; ks < 2; ks++) {
            ldsm4t(vf[ks][0], v_base + (uint32_t)((c0 + ks * 16) * HSTR_B));
            ldsm4t(vf[ks][1], v_base + (uint32_t)((c0 + ks * 16) * HSTR_B) + 32);
        }

        // P = 2^S in f16x2, packed straight into A-frags
        uint32_t af[2][2][4];
#pragma unroll
        for (int mt = 0; mt < 2; mt++)
#pragma unroll
            for (int nt = 0; nt < 4; nt++) {
                af[mt][nt >> 1][(nt & 1) * 2 + 0] =
                    ex2h2(packh2(p[mt][nt][1], p[mt][nt][0]));
                af[mt][nt >> 1][(nt & 1) * 2 + 1] =
                    ex2h2(packh2(p[mt][nt][3], p[mt][nt][2]));
            }

        // row sums: P x ones (exact f32 accumulation in tensor core)
#pragma unroll
        for (int mt = 0; mt < 2; mt++) {
            mma16(rsacc[mt], af[mt][0], ones2);
            mma16(rsacc[mt], af[mt][1], ones2);
        }

        // O += P V
#pragma unroll
        for (int ks = 0; ks < 2; ks++) {
#pragma unroll
            for (int mt = 0; mt < 2; mt++) {
                mma16(o[mt][0], af[mt][ks], vf[ks][0]);
                mma16(o[mt][1], af[mt][ks], vf[ks][0] + 2);
                mma16(o[mt][2], af[mt][ks], vf[ks][1]);
                mma16(o[mt][3], af[mt][ks], vf[ks][1] + 2);
            }
        }
    }

    // ---- normalize + fp16 staging into Q region (warp-private rows; Q frags
    //      were consumed at init, so no cross-warp hazard -> no __syncthreads) ----
#pragma unroll
    for (int mt = 0; mt < 2; mt++) {
        const float inv0 = 1.0f / rsacc[mt][0];   // rowsum(g)
        const float inv1 = 1.0f / rsacc[mt][2];   // rowsum(g+8)
#pragma unroll
        for (int nt = 0; nt < 4; nt++) {
            uint32_t ad = o_st + (uint32_t)(mt * 16 * HSTR_B) + nt * 16;
            sts32(ad, packh2(o[mt][nt][1] * inv0, o[mt][nt][0] * inv0));
            sts32(ad + 8 * HSTR_B, packh2(o[mt][nt][3] * inv1, o[mt][nt][2] * inv1));
        }
    }
    __syncwarp();

    // ---- epilogue: conv — warp = 2 tokens/iter, lane = d2 channel pair ----
    {
        const int d2   = lane & 15;
        const int side = lane >> 4;
        float w0[9], w1[9];
#pragma unroll
        for (int t = 0; t < 9; t++) {
            w0[t] = Wsm[(2 * d2) * 9 + t];
            w1[t] = Wsm[(2 * d2 + 1) * 9 + t];
        }
        const float b0 = Bsm[2 * d2], b1 = Bsm[2 * d2 + 1];

#pragma unroll
        for (int it = 0; it < 16; it++) {
            const int tok = m0 + it * 2 + side;
            const int h = tok >> 3, w = tok & 7;
            float2 oo = __half22float2(
                *(const __half2*)(smb + QS_B + tok * HSTR_B + d2 * 4));
            float a0 = oo.x + b0;
            float a1 = oo.y + b1;
#pragma unroll
            for (int dh = -1; dh <= 1; dh++) {
                const int hh = h + dh;
                if (hh < 0 || hh >= RES) continue;
#pragma unroll
                for (int dw = -1; dw <= 1; dw++) {
                    const int ww = w + dw;
                    if (ww < 0 || ww >= 8) continue;
                    const int k = hh * 8 + ww;
                    const int t = (dh + 1) * 3 + (dw + 1);
                    float2 fv = __half22float2(
                        *(const __half2*)(smb + VS_B + k * HSTR_B + d2 * 4));
                    a0 += w0[t] * fv.x;
                    a1 += w1[t] * fv.y;
                }
            }
            const int l = dsl * 1024 + h * 32 + iw * 8 + w;
            float* op = out + ((size_t)b * LTOK + l) * CDIM + head * HDV + 2 * d2;
            *(float2*)op = make_float2(a0, a1);
        }
    }
}

extern "C" void kernel_launch(void* const* d_in, const int* in_sizes, int n_in,
                              void* d_out, int out_size)
{
    const float* qkv    = (const float*)d_in[0];
    const float* conv_w = (const float*)d_in[1];
    const float* conv_b = (const float*)d_in[2];
    float* out = (float*)d_out;

    cudaFuncSetAttribute(lepe_attn_h16,
                         cudaFuncAttributeMaxDynamicSharedMemorySize, SMEM_BYTES);
    lepe_attn_h16<<<2048, NT, SMEM_BYTES>>>(qkv, conv_w, conv_b, out);
}

// round 14
// speedup vs baseline: 1.1483x; 1.0095x over previous
#include <cuda_runtime.h>
#include <cuda_fp16.h>
#include <stdint.h>

#define RES    32
#define BATCH  2
#define LTOK   32768
#define CDIM   256
#define HEADS  8
#define HDV    32
#define SWIN   256
// scale * log2(e): exp(s) == 2^(s*log2e), folded into Q pre-scale
#define SCALEE 0.25505654201513125f

#define NT     256
#define HSTR_B 80      // fp16 tile row stride: 40 halves = 80B (ldsm conflict-free)

// byte offsets in smem
#define QS_B   0        // Q fp16 [256][40]; later fp16 O staging (same footprint)
#define KS_B   20480    // K fp16 [256][40]
#define VS_B   40960    // V fp16 [256][40]  (ldsm operand)
#define VC_B   61440    // V fp16 [256][32]  compact 64B rows (conv operand)
#define W_B    77824    // conv w, 288 fp32
#define BI_B   78976    // conv b, 32 fp32
#define SMEM_BYTES 79104

__device__ __forceinline__ uint32_t h2u(__half2 h) {
    return *reinterpret_cast<uint32_t*>(&h);
}
__device__ __forceinline__ uint32_t smem_u32(const void* p) {
    uint32_t a;
    asm("{ .reg .u64 t; cvta.to.shared.u64 t, %1; cvt.u32.u64 %0, t; }" : "=r"(a) : "l"(p));
    return a;
}
__device__ __forceinline__ uint32_t packh2(float hi, float lo) {
    uint32_t r;
    asm("cvt.rn.f16x2.f32 %0, %1, %2;" : "=r"(r) : "f"(hi), "f"(lo));
    return r;
}
__device__ __forceinline__ uint32_t ex2h2(uint32_t x) {
    uint32_t r;
    asm("ex2.approx.f16x2 %0, %1;" : "=r"(r) : "r"(x));
    return r;
}
__device__ __forceinline__ void ldsm4(uint32_t* r, uint32_t addr) {
    asm volatile("ldmatrix.sync.aligned.m8n8.x4.shared.b16 {%0,%1,%2,%3}, [%4];"
        : "=r"(r[0]), "=r"(r[1]), "=r"(r[2]), "=r"(r[3]) : "r"(addr));
}
__device__ __forceinline__ void ldsm4t(uint32_t* r, uint32_t addr) {
    asm volatile("ldmatrix.sync.aligned.m8n8.x4.trans.shared.b16 {%0,%1,%2,%3}, [%4];"
        : "=r"(r[0]), "=r"(r[1]), "=r"(r[2]), "=r"(r[3]) : "r"(addr));
}
__device__ __forceinline__ void sts32(uint32_t addr, uint32_t v) {
    asm volatile("st.shared.b32 [%0], %1;" :: "r"(addr), "r"(v) : "memory");
}
// D(f32) += A(f16) * B(f16),  m16n8k16
__device__ __forceinline__ void mma16(float* d, const uint32_t* a, const uint32_t* b) {
    asm("mma.sync.aligned.m16n8k16.row.col.f32.f16.f16.f32 "
        "{%0,%1,%2,%3}, {%4,%5,%6,%7}, {%8,%9}, {%0,%1,%2,%3};"
        : "+f"(d[0]), "+f"(d[1]), "+f"(d[2]), "+f"(d[3])
        : "r"(a[0]), "r"(a[1]), "r"(a[2]), "r"(a[3]), "r"(b[0]), "r"(b[1]));
}

__global__ void __launch_bounds__(NT, 2)
lepe_attn_h16(const float* __restrict__ qkv,
              const float* __restrict__ conv_w,
              const float* __restrict__ conv_b,
              float* __restrict__ out)
{
    extern __shared__ float smem[];
    char* smb = (char*)smem;
    float* Wsm = (float*)(smb + W_B);
    float* Bsm = (float*)(smb + BI_B);
    const uint32_t sb = smem_u32(smem);

    const int tid  = threadIdx.x;
    const int lane = tid & 31;
    const int warp = tid >> 5;
    const int g    = lane >> 2;
    const int tg   = lane & 3;
    const int m0   = warp * 32;

    const int head = blockIdx.x & 7;
    const int wi   = blockIdx.x >> 3;
    const int b    = wi >> 7;
    const int dsl  = (wi >> 2) & 31;
    const int iw   = wi & 3;

    // ---- stage Q/K/V, coalesced: 8 lanes cooperate on one token row ----
    {
        const int piece = lane & 7;
        const size_t qkv_k = (size_t)BATCH * LTOK * CDIM;
#pragma unroll
        for (int it = 0; it < 8; it++) {
            const int tok = m0 + it * 4 + (lane >> 3);
            const int l = dsl * 1024 + (tok >> 3) * 32 + iw * 8 + (tok & 7);
            const size_t base = ((size_t)b * LTOK + l) * CDIM + head * HDV + piece * 4;
            const uint32_t sad = (uint32_t)(tok * HSTR_B + piece * 8);
            float4 qq = *(const float4*)(qkv + base);
            *(uint2*)(smb + QS_B + sad) = make_uint2(
                h2u(__floats2half2_rn(qq.x * SCALEE, qq.y * SCALEE)),
                h2u(__floats2half2_rn(qq.z * SCALEE, qq.w * SCALEE)));
            float4 kk = *(const float4*)(qkv + qkv_k + base);
            *(uint2*)(smb + KS_B + sad) = make_uint2(
                h2u(__floats2half2_rn(kk.x, kk.y)),
                h2u(__floats2half2_rn(kk.z, kk.w)));
            float4 vv = *(const float4*)(qkv + 2 * qkv_k + base);
            uint2 vh = make_uint2(
                h2u(__floats2half2_rn(vv.x, vv.y)),
                h2u(__floats2half2_rn(vv.z, vv.w)));
            *(uint2*)(smb + VS_B + sad) = vh;                            // ldsm copy
            *(uint2*)(smb + VC_B + tok * 64 + piece * 8) = vh;           // conv copy
        }
        for (int i = tid; i < 9 * HDV; i += NT) Wsm[i] = conv_w[head * HDV * 9 + i];
        if (tid < HDV) Bsm[tid] = conv_b[head * HDV + tid];
    }
    __syncthreads();

    const int lane7 = lane & 7;
    const int lb8   = (lane >> 3) & 1;
    const int lb16  = (lane >> 4) & 1;
    const uint32_t a_base = sb + QS_B + (uint32_t)(m0 + lane7 + lb8 * 8) * HSTR_B + lb16 * 16;
    const uint32_t k_base = sb + KS_B + (uint32_t)(lane7 + lb16 * 8) * HSTR_B + lb8 * 16;
    const uint32_t v_base = sb + VS_B + (uint32_t)(lane7 + lb8 * 8) * HSTR_B + lb16 * 16;
    // fp16 O staging over Q region: row (m0+g) stride 80B, half2 at col 2tg
    const uint32_t o_st = sb + QS_B + (uint32_t)(m0 + g) * HSTR_B + tg * 4;

    // ---- Q fragments: 2 m-tiles x 2 k-steps ----
    uint32_t qf[2][2][4];
#pragma unroll
    for (int mt = 0; mt < 2; mt++)
#pragma unroll
        for (int ks = 0; ks < 2; ks++)
            ldsm4(qf[mt][ks], a_base + mt * (16 * HSTR_B) + ks * 32);

    float o[2][4][4];
    float rsacc[2][4];   // row sums via P x ones MMA: c0=rowsum(g), c2=rowsum(g+8)
    const uint32_t ones2[2] = {0x3C003C00u, 0x3C003C00u};
#pragma unroll
    for (int mt = 0; mt < 2; mt++) {
#pragma unroll
        for (int i = 0; i < 4; i++) rsacc[mt][i] = 0.f;
#pragma unroll
        for (int nt = 0; nt < 4; nt++)
#pragma unroll
            for (int i = 0; i < 4; i++) o[mt][nt][i] = 0.f;
    }

    // ---- main loop: 8 chunks of 32 keys ----
    for (int c0 = 0; c0 < SWIN; c0 += 32) {
        float p[2][4][4];
#pragma unroll
        for (int mt = 0; mt < 2; mt++)
#pragma unroll
            for (int nt = 0; nt < 4; nt++)
#pragma unroll
                for (int i = 0; i < 4; i++) p[mt][nt][i] = 0.f;

        // S = Q K^T
#pragma unroll
        for (int ks = 0; ks < 2; ks++) {
            uint32_t kf0[4], kf1[4];
            ldsm4(kf0, k_base + (uint32_t)(c0 * HSTR_B) + ks * 32);
            ldsm4(kf1, k_base + (uint32_t)((c0 + 16) * HSTR_B) + ks * 32);
#pragma unroll
            for (int mt = 0; mt < 2; mt++) {
                mma16(p[mt][0], qf[mt][ks], kf0);
                mma16(p[mt][1], qf[mt][ks], kf0 + 2);
                mma16(p[mt][2], qf[mt][ks], kf1);
                mma16(p[mt][3], qf[mt][ks], kf1 + 2);
            }
        }

        // V fragments hoisted: independent of exp chain, latency hides behind it
        uint32_t vf[2][2][4];
#pragma unroll
        for (int ks = 0; ks < 2; ks++) {
            ldsm4t(vf[ks][0], v_base + (uint32_t)((c0 + ks * 16) * HSTR_B));
            ldsm4t(vf[ks][1], v_base + (uint32_t)((c0 + ks * 16) * HSTR_B) + 32);
        }

        // P = 2^S in f16x2, packed straight into A-frags
        uint32_t af[2][2][4];
#pragma unroll
        for (int mt = 0; mt < 2; mt++)
#pragma unroll
            for (int nt = 0; nt < 4; nt++) {
                af[mt][nt >> 1][(nt & 1) * 2 + 0] =
                    ex2h2(packh2(p[mt][nt][1], p[mt][nt][0]));
                af[mt][nt >> 1][(nt & 1) * 2 + 1] =
                    ex2h2(packh2(p[mt][nt][3], p[mt][nt][2]));
            }

        // row sums: P x ones (exact f32 accumulation in tensor core)
#pragma unroll
        for (int mt = 0; mt < 2; mt++) {
            mma16(rsacc[mt], af[mt][0], ones2);
            mma16(rsacc[mt], af[mt][1], ones2);
        }

        // O += P V
#pragma unroll
        for (int ks = 0; ks < 2; ks++) {
#pragma unroll
            for (int mt = 0; mt < 2; mt++) {
                mma16(o[mt][0], af[mt][ks], vf[ks][0]);
                mma16(o[mt][1], af[mt][ks], vf[ks][0] + 2);
                mma16(o[mt][2], af[mt][ks], vf[ks][1]);
                mma16(o[mt][3], af[mt][ks], vf[ks][1] + 2);
            }
        }
    }

    // ---- normalize + fp16 staging into Q region (warp-private rows) ----
#pragma unroll
    for (int mt = 0; mt < 2; mt++) {
        const float inv0 = 1.0f / rsacc[mt][0];   // rowsum(g)
        const float inv1 = 1.0f / rsacc[mt][2];   // rowsum(g+8)
#pragma unroll
        for (int nt = 0; nt < 4; nt++) {
            uint32_t ad = o_st + (uint32_t)(mt * 16 * HSTR_B) + nt * 16;
            sts32(ad, packh2(o[mt][nt][1] * inv0, o[mt][nt][0] * inv0));
            sts32(ad + 8 * HSTR_B, packh2(o[mt][nt][3] * inv1, o[mt][nt][2] * inv1));
        }
    }
    __syncwarp();

    // ---- epilogue: conv — warp = 2 tokens/iter, lane = d2 channel pair;
    //      V taps from compact VC (token pair = one 128B line = 1 wavefront) ----
    {
        const int d2   = lane & 15;
        const int side = lane >> 4;
        float w0[9], w1[9];
#pragma unroll
        for (int t = 0; t < 9; t++) {
            w0[t] = Wsm[(2 * d2) * 9 + t];
            w1[t] = Wsm[(2 * d2 + 1) * 9 + t];
        }
        const float b0 = Bsm[2 * d2], b1 = Bsm[2 * d2 + 1];

#pragma unroll
        for (int it = 0; it < 16; it++) {
            const int tok = m0 + it * 2 + side;
            const int h = tok >> 3, w = tok & 7;
            float2 oo = __half22float2(
                *(const __half2*)(smb + QS_B + tok * HSTR_B + d2 * 4));
            float a0 = oo.x + b0;
            float a1 = oo.y + b1;
#pragma unroll
            for (int dh = -1; dh <= 1; dh++) {
                const int hh = h + dh;
                if (hh < 0 || hh >= RES) continue;
#pragma unroll
                for (int dw = -1; dw <= 1; dw++) {
                    const int ww = w + dw;
                    if (ww < 0 || ww >= 8) continue;
                    const int k = hh * 8 + ww;
                    const int t = (dh + 1) * 3 + (dw + 1);
                    float2 fv = __half22float2(
                        *(const __half2*)(smb + VC_B + k * 64 + d2 * 4));
                    a0 += w0[t] * fv.x;
                    a1 += w1[t] * fv.y;
                }
            }
            const int l = dsl * 1024 + h * 32 + iw * 8 + w;
            float* op = out + ((size_t)b * LTOK + l) * CDIM + head * HDV + 2 * d2;
            *(float2*)op = make_float2(a0, a1);
        }
    }
}

extern "C" void kernel_launch(void* const* d_in, const int* in_sizes, int n_in,
                              void* d_out, int out_size)
{
    const float* qkv    = (const float*)d_in[0];
    const float* conv_w = (const float*)d_in[1];
    const float* conv_b = (const float*)d_in[2];
    float* out = (float*)d_out;

    cudaFuncSetAttribute(lepe_attn_h16,
                         cudaFuncAttributeMaxDynamicSharedMemorySize, SMEM_BYTES);
    lepe_attn_h16<<<2048, NT, SMEM_BYTES>>>(qkv, conv_w, conv_b, out);
}